// round 1
// baseline (speedup 1.0000x reference)
#include <cuda_runtime.h>
#include <cstdint>

// Problem constants (fixed by the reference)
#define OUT_N 11008
#define IN_K  4096
#define GS    128
#define NG    (IN_K / GS)        // 32 groups per row
#define M_TOK 8

// Tiling
#define BLOCK            256
#define WARPS            (BLOCK / 32)          // 8
#define T_ROWS           4                      // output rows per warp
#define ROWS_PER_BLOCK   (WARPS * T_ROWS)       // 32
#define CHUNK            1024                   // k-columns of x staged in smem
#define GPC              (CHUNK / GS)           // 8 groups per chunk
#define NCHUNK           (IN_K / CHUNK)         // 4

__global__ __launch_bounds__(BLOCK)
void qlinear_pergrp_kernel(const float* __restrict__ x,
                           const int*   __restrict__ qw,
                           const int*   __restrict__ qz,
                           const float* __restrict__ sc,
                           float*       __restrict__ out)
{
    // x chunk, [m][k] layout: lane reads float4 at contiguous 16B stride -> conflict-free
    __shared__ float4 xs4[M_TOK][CHUNK / 4];        // 32 KB
    // per (local row, group): {scale s, zf = (float)z + 2^23}
    __shared__ float2 sz[ROWS_PER_BLOCK][NG];       // 8 KB

    const int tid  = threadIdx.x;
    const int warp = tid >> 5;
    const int lane = tid & 31;
    const int row_blk = blockIdx.x * ROWS_PER_BLOCK;

    // ---- precompute per-group constants into smem ----
    for (int e = tid; e < ROWS_PER_BLOCK * NG; e += BLOCK) {
        const int lr = e >> 5;          // local row
        const int g  = e & (NG - 1);    // group
        const int gr = row_blk + lr;
        const float s = sc[gr * NG + g];
        const int   z = qz[gr * NG + g];
        sz[lr][g] = make_float2(s, (float)z + 8388608.0f);   // zf = z + 2^23 (exact)
    }

    const int row0 = row_blk + warp * T_ROWS;
    const int4* qrow[T_ROWS];
#pragma unroll
    for (int r = 0; r < T_ROWS; r++)
        qrow[r] = (const int4*)(qw + (size_t)(row0 + r) * IN_K);

    float acc[T_ROWS][M_TOK];
#pragma unroll
    for (int r = 0; r < T_ROWS; r++)
#pragma unroll
        for (int m = 0; m < M_TOK; m++) acc[r][m] = 0.0f;

    const float4* xg = (const float4*)x;   // x[m][k] as float4: index m*(IN_K/4) + k/4

    for (int c = 0; c < NCHUNK; c++) {
        __syncthreads();   // protect previous chunk's readers (and sz on first iter)
        // cooperative load of x chunk: 8 * 256 float4, fully coalesced
#pragma unroll
        for (int it = 0; it < (M_TOK * (CHUNK / 4)) / BLOCK; it++) {
            const int idx = it * BLOCK + tid;
            const int m  = idx >> 8;          // / (CHUNK/4=256)
            const int i4 = idx & 255;
            xs4[m][i4] = xg[m * (IN_K / 4) + c * (CHUNK / 4) + i4];
        }
        __syncthreads();

#pragma unroll 2
        for (int jj = 0; jj < GPC; jj++) {
            const int g  = c * GPC + jj;
            const int kq = c * (CHUNK / 4) + jj * (GS / 4) + lane;   // int4 idx in row

            // x for this lane's 4 k-positions, all 8 tokens (reused across T_ROWS)
            float4 xv[M_TOK];
#pragma unroll
            for (int m = 0; m < M_TOK; m++)
                xv[m] = xs4[m][jj * (GS / 4) + lane];

#pragma unroll
            for (int r = 0; r < T_ROWS; r++) {
                const int4 q4 = __ldcs(&qrow[r][kq]);   // streaming: don't pollute L2
                const float2 szv = sz[warp * T_ROWS + r][g];  // uniform -> broadcast
                const float s = szv.x, zf = szv.y;
                // exact dequant: as_float(q | 0x4B000000) == 2^23 + q ; (2^23+q)-(2^23+z)
                // is Sterbenz-exact == q - z
                const float w0 = (__int_as_float(q4.x | 0x4B000000) - zf) * s;
                const float w1 = (__int_as_float(q4.y | 0x4B000000) - zf) * s;
                const float w2 = (__int_as_float(q4.z | 0x4B000000) - zf) * s;
                const float w3 = (__int_as_float(q4.w | 0x4B000000) - zf) * s;
#pragma unroll
                for (int m = 0; m < M_TOK; m++) {
                    acc[r][m] = fmaf(w0, xv[m].x, acc[r][m]);
                    acc[r][m] = fmaf(w1, xv[m].y, acc[r][m]);
                    acc[r][m] = fmaf(w2, xv[m].z, acc[r][m]);
                    acc[r][m] = fmaf(w3, xv[m].w, acc[r][m]);
                }
            }
        }
    }

    // ---- intra-warp reduction over the k-split ----
#pragma unroll
    for (int r = 0; r < T_ROWS; r++)
#pragma unroll
        for (int m = 0; m < M_TOK; m++) {
#pragma unroll
            for (int off = 16; off > 0; off >>= 1)
                acc[r][m] += __shfl_xor_sync(0xffffffffu, acc[r][m], off);
        }

    if (lane == 0) {
#pragma unroll
        for (int r = 0; r < T_ROWS; r++)
#pragma unroll
            for (int m = 0; m < M_TOK; m++)
                out[m * OUT_N + (row0 + r)] = acc[r][m];
    }
}

extern "C" void kernel_launch(void* const* d_in, const int* in_sizes, int n_in,
                              void* d_out, int out_size)
{
    const float* x  = (const float*)d_in[0];   // [8, 4096] f32
    const int*   qw = (const int*)  d_in[1];   // [11008, 4096] int32 in [0,15]
    const int*   qz = (const int*)  d_in[2];   // [11008, 32] int32
    const float* sc = (const float*)d_in[3];   // [11008, 32] f32
    float* out = (float*)d_out;                // [8, 11008] f32

    const int grid = OUT_N / ROWS_PER_BLOCK;   // 344
    qlinear_pergrp_kernel<<<grid, BLOCK>>>(x, qw, qz, sc, out);
}

// round 2
// speedup vs baseline: 1.4126x; 1.4126x over previous
#include <cuda_runtime.h>
#include <cstdint>

// Problem constants
#define OUT_N 11008
#define IN_K  4096
#define GS    128
#define NG    32          // groups per row
#define M_TOK 8

// Tiling
#define BLOCK            256
#define WARPS            8
#define T_ROWS           2                      // output rows per warp
#define ROWS_PER_BLOCK   (WARPS * T_ROWS)       // 16 -> grid 688
#define CHUNK            1024                   // k-columns of x staged in smem
#define GPC              (CHUNK / GS)           // 8 groups per chunk
#define NCHUNK           (IN_K / CHUNK)         // 4

typedef unsigned long long u64;

// ---- packed f32x2 helpers (Blackwell FFMA2 path; ptxas won't emit from C++) ----
__device__ __forceinline__ u64 pkf(float lo, float hi) {
    u64 r; asm("mov.b64 %0, {%1, %2};" : "=l"(r) : "f"(lo), "f"(hi)); return r;
}
__device__ __forceinline__ u64 pki(unsigned lo, unsigned hi) {
    u64 r; asm("mov.b64 %0, {%1, %2};" : "=l"(r) : "r"(lo), "r"(hi)); return r;
}
__device__ __forceinline__ u64 add2(u64 a, u64 b) {
    u64 r; asm("add.rn.f32x2 %0, %1, %2;" : "=l"(r) : "l"(a), "l"(b)); return r;
}
__device__ __forceinline__ u64 mul2(u64 a, u64 b) {
    u64 r; asm("mul.rn.f32x2 %0, %1, %2;" : "=l"(r) : "l"(a), "l"(b)); return r;
}
__device__ __forceinline__ u64 fma2(u64 a, u64 b, u64 c) {
    u64 r; asm("fma.rn.f32x2 %0, %1, %2, %3;" : "=l"(r) : "l"(a), "l"(b), "l"(c)); return r;
}
__device__ __forceinline__ float2 upk(u64 a) {
    float lo, hi; asm("mov.b64 {%0, %1}, %2;" : "=f"(lo), "=f"(hi) : "l"(a));
    return make_float2(lo, hi);
}

__global__ void __launch_bounds__(BLOCK, 2)
qlinear_pergrp_kernel(const float* __restrict__ x,
                      const int*   __restrict__ qw,
                      const int*   __restrict__ qz,
                      const float* __restrict__ sc,
                      float*       __restrict__ out)
{
    // x chunk, [m][k/4] float4: lane loads are contiguous 16B -> conflict-free LDS.128
    __shared__ float4 xs4[M_TOK][CHUNK / 4];          // 32 KB
    // per (local row, group): {s, s, -(z+2^23), -(z+2^23)} pre-duplicated for f32x2
    __shared__ float4 szp[ROWS_PER_BLOCK][NG];        // 8 KB

    const int tid  = threadIdx.x;
    const int warp = tid >> 5;
    const int lane = tid & 31;
    const int row_blk = blockIdx.x * ROWS_PER_BLOCK;

    // ---- precompute per-group constants (duplicated halves) ----
    for (int e = tid; e < ROWS_PER_BLOCK * NG; e += BLOCK) {
        const int lr = e >> 5;
        const int g  = e & (NG - 1);
        const int gr = row_blk + lr;
        const float s  = sc[gr * NG + g];
        const float nz = -((float)qz[gr * NG + g] + 8388608.0f);  // -(z + 2^23), exact
        szp[lr][g] = make_float4(s, s, nz, nz);
    }
    // (first chunk's __syncthreads covers szp visibility)

    const int row0 = row_blk + warp * T_ROWS;
    const int4* q0 = (const int4*)(qw + (size_t)row0 * IN_K);
    const int4* q1 = q0 + (IN_K / 4);

    u64 acc[T_ROWS][M_TOK];
#pragma unroll
    for (int r = 0; r < T_ROWS; r++)
#pragma unroll
        for (int m = 0; m < M_TOK; m++) acc[r][m] = 0ULL;

    // ---- depth-2 weight prefetch (groups g and g+1 in flight) ----
    int4 qb0[T_ROWS], qb1[T_ROWS];
    qb0[0] = __ldcs(q0 + lane);        qb0[1] = __ldcs(q1 + lane);
    qb1[0] = __ldcs(q0 + 32 + lane);   qb1[1] = __ldcs(q1 + 32 + lane);

    const float4* xg = (const float4*)x;

    for (int c = 0; c < NCHUNK; c++) {
        __syncthreads();
        // cooperative x chunk load: 2048 float4, fully coalesced (L2-resident)
#pragma unroll
        for (int it = 0; it < (M_TOK * (CHUNK / 4)) / BLOCK; it++) {
            const int idx = it * BLOCK + tid;
            const int m  = idx >> 8;
            const int i4 = idx & 255;
            xs4[m][i4] = xg[m * (IN_K / 4) + c * (CHUNK / 4) + i4];
        }
        __syncthreads();

#pragma unroll
        for (int jj = 0; jj < GPC; jj++) {
            const int g = c * GPC + jj;

            // rotate prefetch buffers (parity known at compile time: g&1 == jj&1)
            int4 qc[T_ROWS];
            if (jj & 1) { qc[0] = qb1[0]; qc[1] = qb1[1]; }
            else        { qc[0] = qb0[0]; qc[1] = qb0[1]; }

            const int gn = g + 2;
            if (gn < NG) {
                const int off = gn * 32 + lane;
                if (jj & 1) { qb1[0] = __ldcs(q0 + off); qb1[1] = __ldcs(q1 + off); }
                else        { qb0[0] = __ldcs(q0 + off); qb0[1] = __ldcs(q1 + off); }
            }

            // x values for this lane's 4 k-positions, all 8 tokens, k-packed
            u64 x01[M_TOK], x23[M_TOK];
#pragma unroll
            for (int m = 0; m < M_TOK; m++) {
                const float4 xv = xs4[m][jj * 32 + lane];
                x01[m] = pkf(xv.x, xv.y);       // adjacent regs -> free pair
                x23[m] = pkf(xv.z, xv.w);
            }

#pragma unroll
            for (int r = 0; r < T_ROWS; r++) {
                const float4 szv = szp[warp * T_ROWS + r][g];   // uniform broadcast
                const u64 ss = pkf(szv.x, szv.y);
                const u64 zz = pkf(szv.z, szv.w);               // {-(z+2^23)} x2
                const int4 q4 = qc[r];
                // as_float(q | 0x4B000000) == 2^23 + q ; (2^23+q) + (-(2^23+z)) exact
                const u64 q01 = pki((unsigned)q4.x | 0x4B000000u,
                                    (unsigned)q4.y | 0x4B000000u);
                const u64 q23 = pki((unsigned)q4.z | 0x4B000000u,
                                    (unsigned)q4.w | 0x4B000000u);
                const u64 w01 = mul2(add2(q01, zz), ss);
                const u64 w23 = mul2(add2(q23, zz), ss);
#pragma unroll
                for (int m = 0; m < M_TOK; m++) {
                    acc[r][m] = fma2(w01, x01[m], acc[r][m]);
                    acc[r][m] = fma2(w23, x23[m], acc[r][m]);
                }
            }
        }
    }

    // ---- fold f32x2 halves, then intra-warp reduction over the k-split ----
#pragma unroll
    for (int r = 0; r < T_ROWS; r++)
#pragma unroll
        for (int m = 0; m < M_TOK; m++) {
            const float2 v = upk(acc[r][m]);
            float s = v.x + v.y;
#pragma unroll
            for (int off = 16; off > 0; off >>= 1)
                s += __shfl_xor_sync(0xffffffffu, s, off);
            if (lane == 0)
                out[m * OUT_N + (row0 + r)] = s;
        }
}

extern "C" void kernel_launch(void* const* d_in, const int* in_sizes, int n_in,
                              void* d_out, int out_size)
{
    const float* x  = (const float*)d_in[0];   // [8, 4096] f32
    const int*   qw = (const int*)  d_in[1];   // [11008, 4096] int32 in [0,15]
    const int*   qz = (const int*)  d_in[2];   // [11008, 32] int32
    const float* sc = (const float*)d_in[3];   // [11008, 32] f32
    float* out = (float*)d_out;                // [8, 11008] f32

    const int grid = OUT_N / ROWS_PER_BLOCK;   // 688
    qlinear_pergrp_kernel<<<grid, BLOCK>>>(x, qw, qz, sc, out);
}